// round 16
// baseline (speedup 1.0000x reference)
#include <cuda_runtime.h>
#include <math.h>
#include <stdint.h>

#define Bn 8
#define Ln 1024
#define DM 256
#define DI 512
#define NH 16
#define HD 32
#define DS 128
#define CONVD 768
#define DIP 1296
#define Qc 64
#define NC 16   /* Ln/Qc */

// ---------------- scratch (device globals; no mallocs allowed) ----------------
__device__ float g_zx[Bn*Ln*DIP];       // in-proj output
__device__ float g_xs[Bn*Ln*DI];        // conv output, x part (raw, no dt)
__device__ float g_Bmat[Bn*Ln*DS];
__device__ float g_Cmat[Bn*Ln*DS];
__device__ float g_dt[Bn*Ln*NH];
__device__ float g_G[Bn*NC*Qc*Qc];      // TRANSPOSED Gram: Gt[s][t] = C[t]·B[s]
__device__ float g_Acs[Bn*NC*NH*Qc];    // per-chunk inclusive cumsum of dA
__device__ float g_Y[Bn*Ln*DI];         // SSD output accumulator
__device__ float g_st[Bn*NC*NH*HD*DS];  // chunk states -> then prev states
__device__ float g_yf[Bn*Ln*DI];        // gated + rmsnormed
__device__ float g_op[Bn*DM*Ln];        // out-proj, already transposed (b,m,l)
__device__ float g_gnpart[Bn*8*16*2];   // per-(b,g,by) partial sum/sumsq from k5

// ---------------- fast math helpers -----------------------------------------
__device__ __forceinline__ float fsilu(float x){
    return __fdividef(x, 1.f + __expf(-x));
}
__device__ __forceinline__ float fmish(float v){
    float t = 1.f + __expf(v);
    return v - v * __fdividef(2.f, t*t + 1.f);
}

// ---------------- tf32 mma helpers -----------------------------------------
__device__ __forceinline__ uint32_t f2tf32(float f){
    uint32_t r; asm("cvt.rna.tf32.f32 %0, %1;" : "=r"(r) : "f"(f)); return r;
}
__device__ __forceinline__ void mma_tf32(float* c, const uint32_t* a, const uint32_t* b){
    asm volatile("mma.sync.aligned.m16n8k8.row.col.f32.tf32.tf32.f32 "
        "{%0,%1,%2,%3}, {%4,%5,%6,%7}, {%8,%9}, {%0,%1,%2,%3};\n"
        : "+f"(c[0]), "+f"(c[1]), "+f"(c[2]), "+f"(c[3])
        : "r"(a[0]), "r"(a[1]), "r"(a[2]), "r"(a[3]),
          "r"(b[0]), "r"(b[1]));
}

// ---------------- K1: in-proj GEMM via tf32 MMA ----------------------------
// zx[m,n] = sum_c x[b,c,l] * W_in[n,c];  m=(b,l): M=8192, N=1296, K=256
__global__ void __launch_bounds__(256) k1_mma(const float* __restrict__ x,
                                              const float* __restrict__ W){
    __shared__ uint32_t As[2][16][132];   // [k][m]
    __shared__ uint32_t Bs[2][16][132];   // [k][n]
    const int n0 = blockIdx.x * 128;
    const int m0 = blockIdx.y * 128;
    const int b  = m0 >> 10;
    const int l0 = m0 & 1023;
    const int tid = threadIdx.x;
    const int wid = tid >> 5, lane = tid & 31;
    const int wm = wid >> 2, wn = wid & 3;      // warp grid 2(m) x 4(n)
    const int lr = lane >> 2, lc = lane & 3;
    float acc[4][4][4] = {};

    const int a_kk = tid >> 5;
    const int a_mm = (tid & 31) << 2;
    const int b_n  = tid & 127;
    const int b_kq = tid >> 7;
    const int n_glob = n0 + b_n;

    #pragma unroll
    for (int i = 0; i < 2; i++){
        int kk = a_kk + i*8;
        float4 v = *reinterpret_cast<const float4*>(&x[((size_t)b*DM + kk)*Ln + l0 + a_mm]);
        uint32_t* p = &As[0][kk][a_mm];
        p[0]=f2tf32(v.x); p[1]=f2tf32(v.y); p[2]=f2tf32(v.z); p[3]=f2tf32(v.w);
    }
    #pragma unroll
    for (int i = 0; i < 2; i++){
        int kq = b_kq + i*2;
        float4 v = make_float4(0.f,0.f,0.f,0.f);
        if (n_glob < DIP) v = *reinterpret_cast<const float4*>(&W[(size_t)n_glob*DM + kq*4]);
        Bs[0][kq*4+0][b_n]=f2tf32(v.x);
        Bs[0][kq*4+1][b_n]=f2tf32(v.y);
        Bs[0][kq*4+2][b_n]=f2tf32(v.z);
        Bs[0][kq*4+3][b_n]=f2tf32(v.w);
    }
    __syncthreads();

    for (int s = 0; s < 16; s++){
        int buf = s & 1;
        float4 av[2], bv[2];
        if (s < 15){
            int c0 = (s+1)*16;
            #pragma unroll
            for (int i = 0; i < 2; i++){
                int kk = a_kk + i*8;
                av[i] = *reinterpret_cast<const float4*>(&x[((size_t)b*DM + c0 + kk)*Ln + l0 + a_mm]);
            }
            #pragma unroll
            for (int i = 0; i < 2; i++){
                int kq = b_kq + i*2;
                bv[i] = (n_glob < DIP)
                    ? *reinterpret_cast<const float4*>(&W[(size_t)n_glob*DM + c0 + kq*4])
                    : make_float4(0.f,0.f,0.f,0.f);
            }
        }
        #pragma unroll
        for (int ksub = 0; ksub < 2; ksub++){
            int ks = ksub*8;
            uint32_t af[4][4], bf[4][2];
            #pragma unroll
            for (int mi = 0; mi < 4; mi++){
                int mr = wm*64 + mi*16 + lr;
                af[mi][0] = As[buf][ks+lc][mr];
                af[mi][1] = As[buf][ks+lc][mr+8];
                af[mi][2] = As[buf][ks+4+lc][mr];
                af[mi][3] = As[buf][ks+4+lc][mr+8];
            }
            #pragma unroll
            for (int ni = 0; ni < 4; ni++){
                int nc = wn*32 + ni*8 + lr;
                bf[ni][0] = Bs[buf][ks+lc][nc];
                bf[ni][1] = Bs[buf][ks+4+lc][nc];
            }
            #pragma unroll
            for (int mi = 0; mi < 4; mi++)
                #pragma unroll
                for (int ni = 0; ni < 4; ni++)
                    mma_tf32(acc[mi][ni], af[mi], bf[ni]);
        }
        if (s < 15){
            #pragma unroll
            for (int i = 0; i < 2; i++){
                int kk = a_kk + i*8;
                uint32_t* p = &As[buf^1][kk][a_mm];
                p[0]=f2tf32(av[i].x); p[1]=f2tf32(av[i].y); p[2]=f2tf32(av[i].z); p[3]=f2tf32(av[i].w);
            }
            #pragma unroll
            for (int i = 0; i < 2; i++){
                int kq = b_kq + i*2;
                Bs[buf^1][kq*4+0][b_n]=f2tf32(bv[i].x);
                Bs[buf^1][kq*4+1][b_n]=f2tf32(bv[i].y);
                Bs[buf^1][kq*4+2][b_n]=f2tf32(bv[i].z);
                Bs[buf^1][kq*4+3][b_n]=f2tf32(bv[i].w);
            }
            __syncthreads();
        }
    }
    #pragma unroll
    for (int mi = 0; mi < 4; mi++){
        int m = m0 + wm*64 + mi*16 + lr;
        #pragma unroll
        for (int ni = 0; ni < 4; ni++){
            int n = n0 + wn*32 + ni*8 + lc*2;
            if (n < DIP){
                g_zx[(size_t)m*DIP + n]       = acc[mi][ni][0];
                g_zx[(size_t)m*DIP + n + 1]   = acc[mi][ni][1];
                g_zx[(size_t)(m+8)*DIP + n]   = acc[mi][ni][2];
                g_zx[(size_t)(m+8)*DIP + n+1] = acc[mi][ni][3];
            }
        }
    }
}

// ---------------- K2: depthwise conv + SiLU + split, and dt=softplus -------
__global__ void __launch_bounds__(224) k2_conv(const float* __restrict__ conv_w,
                        const float* __restrict__ conv_b,
                        const float* __restrict__ dt_bias){
    int tid = threadIdx.x;
    int l0 = blockIdx.x*4, b = blockIdx.y;
    if (tid < 192){
        int ch = tid*4;
        float4 cw0 = *reinterpret_cast<const float4*>(conv_w + (ch+0)*4);
        float4 cw1 = *reinterpret_cast<const float4*>(conv_w + (ch+1)*4);
        float4 cw2 = *reinterpret_cast<const float4*>(conv_w + (ch+2)*4);
        float4 cw3 = *reinterpret_cast<const float4*>(conv_w + (ch+3)*4);
        float4 bias = *reinterpret_cast<const float4*>(conv_b + ch);
        float4 v[7];
        #pragma unroll
        for (int k = 0; k < 7; k++){
            int ls = l0 - 3 + k;
            v[k] = (ls >= 0)
                ? *reinterpret_cast<const float4*>(&g_zx[((size_t)b*Ln + ls)*DIP + DI + ch])
                : make_float4(0.f,0.f,0.f,0.f);
        }
        #pragma unroll
        for (int j = 0; j < 4; j++){
            float4 r;
            r.x = fsilu(bias.x + cw0.x*v[j].x + cw0.y*v[j+1].x + cw0.z*v[j+2].x + cw0.w*v[j+3].x);
            r.y = fsilu(bias.y + cw1.x*v[j].y + cw1.y*v[j+1].y + cw1.z*v[j+2].y + cw1.w*v[j+3].y);
            r.z = fsilu(bias.z + cw2.x*v[j].z + cw2.y*v[j+1].z + cw2.z*v[j+2].z + cw2.w*v[j+3].z);
            r.w = fsilu(bias.w + cw3.x*v[j].w + cw3.y*v[j+1].w + cw3.z*v[j+2].w + cw3.w*v[j+3].w);
            size_t row = (size_t)b*Ln + l0 + j;
            if (ch < DI)
                *reinterpret_cast<float4*>(&g_xs[row*DI + ch]) = r;
            else if (ch < DI+DS)
                *reinterpret_cast<float4*>(&g_Bmat[row*DS + (ch-DI)]) = r;
            else
                *reinterpret_cast<float4*>(&g_Cmat[row*DS + (ch-DI-DS)]) = r;
        }
    } else if (tid < 192 + NH){
        int hh = tid - 192;
        float db = dt_bias[hh];
        #pragma unroll
        for (int j = 0; j < 4; j++){
            size_t row = (size_t)b*Ln + l0 + j;
            float v = g_zx[row*DIP + DI + CONVD + hh] + db;
            float sp = (v > 20.f) ? v : log1pf(__expf(v));
            g_dt[row*NH + hh] = sp;
        }
    }
}

// ---------------- S0: Gram Gt[b,c,s,t] = C[t]·B[s] (stored transposed) ------
__global__ void s0_gram(){
    __shared__ float Cs[32][65];
    __shared__ float Bs[32][65];
    int bc = blockIdx.x;            // b*NC + c
    int b = bc / NC, c = bc % NC;
    int l0 = c*Qc;
    int tid = threadIdx.x;
    int tx = tid & 15, ty = tid >> 4;
    float acc[4][4] = {};
    for (int n0 = 0; n0 < DS; n0 += 32){
        #pragma unroll
        for (int k = 0; k < 8; k++){
            int idx = tid + k*256;
            int t = idx >> 5, kk = idx & 31;
            Cs[kk][t] = g_Cmat[((size_t)b*Ln + l0 + t)*DS + n0 + kk];
            Bs[kk][t] = g_Bmat[((size_t)b*Ln + l0 + t)*DS + n0 + kk];
        }
        __syncthreads();
        #pragma unroll
        for (int kk = 0; kk < 32; kk++){
            float a[4], bb[4];
            #pragma unroll
            for (int i = 0; i < 4; i++) a[i]  = Bs[kk][ty*4+i];   // rows = s
            #pragma unroll
            for (int j = 0; j < 4; j++) bb[j] = Cs[kk][tx*4+j];   // cols = t
            #pragma unroll
            for (int i = 0; i < 4; i++)
                #pragma unroll
                for (int j = 0; j < 4; j++) acc[i][j] += a[i]*bb[j];
        }
        __syncthreads();
    }
    #pragma unroll
    for (int i = 0; i < 4; i++)
        #pragma unroll
        for (int j = 0; j < 4; j++)
            g_G[((size_t)bc*Qc + ty*4 + i)*Qc + tx*4 + j] = acc[i][j];
}

// ---------------- S1: per (b,chunk,head): scan, Y_diag(MMA), states(MMA) ----
// Restructured: single-warp pair-scan, all global loads issued at entry,
// 2 barriers total. Se folded into a second X tile (states A operand).
__global__ void __launch_bounds__(256) s1_intra(const float* __restrict__ A_log){
    extern __shared__ float sm[];
    uint32_t* sXT  = (uint32_t*)sm;              // Qc*36  tf32(X*dt)
    uint32_t* sXS  = sXT + Qc*36;                // Qc*36  tf32(X*dt*Se)
    uint32_t* sBT  = sXS + Qc*36;                // Qc*132 tf32(B)
    uint32_t* sWT  = sBT + Qc*132;               // Qc*68  tf32(W^T)
    float*    sAcs = (float*)(sWT + Qc*68);      // Qc
    float*    sdt  = sAcs + Qc;                  // Qc
    int id = blockIdx.x;            // ((b*NC + c)*NH + h)
    int h = id % NH;
    int c = (id / NH) % NC;
    int b = id / (NH*NC);
    int l0 = c*Qc;
    int tid = threadIdx.x;
    int wid = tid >> 5, lane = tid & 31;
    int lr = lane >> 2, lc_ = lane & 3;

    // ---- issue ALL independent global loads up front (full MLP) ----
    const float* Gt = g_G + ((size_t)(b*NC + c)*Qc)*Qc;
    float gv[16];
    #pragma unroll
    for (int k = 0; k < 16; k++){
        int idx = tid + k*256;
        int s_ = idx >> 6, t_ = idx & 63;
        gv[k] = (s_ <= t_) ? Gt[s_*Qc + t_] : 0.f;
    }
    float4 xv[2];
    #pragma unroll
    for (int k = 0; k < 2; k++){
        int idx4 = tid + k*256;
        int t = idx4 >> 3, p4 = (idx4 & 7)*4;
        xv[k] = *reinterpret_cast<const float4*>(&g_xs[(((size_t)b*Ln + l0 + t)*NH + h)*HD + p4]);
    }
    #pragma unroll
    for (int k = 0; k < 8; k++){
        int idx = tid + k*256;
        int t = idx >> 5, c4 = (idx & 31)*4;
        float4 bv = *reinterpret_cast<const float4*>(&g_Bmat[((size_t)b*Ln + l0 + t)*DS + c4]);
        uint4 u;
        u.x = f2tf32(bv.x); u.y = f2tf32(bv.y); u.z = f2tf32(bv.z); u.w = f2tf32(bv.w);
        *reinterpret_cast<uint4*>(&sBT[t*132 + c4]) = u;
    }
    // single-warp pair-scan over 64 elements (warp 0, 2 elems/lane)
    if (tid < 32){
        int t0 = 2*tid, t1 = 2*tid + 1;
        float d0 = g_dt[((size_t)b*Ln + l0 + t0)*NH + h];
        float d1 = g_dt[((size_t)b*Ln + l0 + t1)*NH + h];
        sdt[t0] = d0; sdt[t1] = d1;
        float mA = -__expf(A_log[h]);
        float a0 = d0*mA, a1 = d1*mA;
        float ps = a0 + a1;
        #pragma unroll
        for (int off = 1; off < 32; off <<= 1){
            float u = __shfl_up_sync(0xffffffffu, ps, off);
            if (tid >= off) ps += u;
        }
        float acs1 = ps;
        float acs0 = ps - a1;
        sAcs[t0] = acs0; sAcs[t1] = acs1;
        g_Acs[(size_t)id*Qc + t0] = acs0;
        g_Acs[(size_t)id*Qc + t1] = acs1;
    }
    __syncthreads();

    float tot = sAcs[Qc-1];
    #pragma unroll
    for (int k = 0; k < 2; k++){
        int idx4 = tid + k*256;
        int t = idx4 >> 3, p4 = (idx4 & 7)*4;
        float d = sdt[t];
        float se = __expf(tot - sAcs[t]);
        float x0 = xv[k].x*d, x1 = xv[k].y*d, x2 = xv[k].z*d, x3 = xv[k].w*d;
        uint4 u1, u2;
        u1.x = f2tf32(x0); u1.y = f2tf32(x1); u1.z = f2tf32(x2); u1.w = f2tf32(x3);
        u2.x = f2tf32(x0*se); u2.y = f2tf32(x1*se); u2.z = f2tf32(x2*se); u2.w = f2tf32(x3*se);
        *reinterpret_cast<uint4*>(&sXT[t*36 + p4]) = u1;
        *reinterpret_cast<uint4*>(&sXS[t*36 + p4]) = u2;
    }
    #pragma unroll
    for (int k = 0; k < 16; k++){
        int idx = tid + k*256;
        int s_ = idx >> 6, t_ = idx & 63;
        float w = 0.f;
        if (s_ <= t_) w = gv[k] * __expf(sAcs[t_] - sAcs[s_]);
        sWT[s_*68 + t_] = f2tf32(w);
    }
    __syncthreads();

    if (wid < 4){
        const int m0w = wid*16;
        float acc[4][4] = {};
        const int kmax = 2*(wid+1);   // triangular
        for (int k = 0; k < kmax; k++){
            int ks = k*8;
            uint32_t a[4];
            a[0] = sWT[(ks+lc_)*68   + m0w + lr];
            a[1] = sWT[(ks+lc_)*68   + m0w + lr + 8];
            a[2] = sWT[(ks+4+lc_)*68 + m0w + lr];
            a[3] = sWT[(ks+4+lc_)*68 + m0w + lr + 8];
            #pragma unroll
            for (int ni = 0; ni < 4; ni++){
                uint32_t bf[2];
                bf[0] = sXT[(ks+lc_)*36   + ni*8 + lr];
                bf[1] = sXT[(ks+4+lc_)*36 + ni*8 + lr];
                mma_tf32(acc[ni], a, bf);
            }
        }
        #pragma unroll
        for (int ni = 0; ni < 4; ni++){
            int t = m0w + lr;
            int p = ni*8 + lc_*2;
            size_t gi = (((size_t)b*Ln + l0 + t)*NH + h)*HD + p;
            *reinterpret_cast<float2*>(&g_Y[gi]) = make_float2(acc[ni][0], acc[ni][1]);
            size_t gi2 = gi + (size_t)8*NH*HD;
            *reinterpret_cast<float2*>(&g_Y[gi2]) = make_float2(acc[ni][2], acc[ni][3]);
        }
    } else {
        const int ww = wid - 4;
        const int p0 = (ww & 1)*16, n0 = (ww >> 1)*64;
        float acc[8][4] = {};
        #pragma unroll
        for (int k = 0; k < 8; k++){
            int ks = k*8;
            int t0 = ks + lc_, t1 = ks + 4 + lc_;
            uint32_t a[4];
            a[0] = sXS[t0*36 + p0 + lr];
            a[1] = sXS[t0*36 + p0 + lr + 8];
            a[2] = sXS[t1*36 + p0 + lr];
            a[3] = sXS[t1*36 + p0 + lr + 8];
            #pragma unroll
            for (int ni = 0; ni < 8; ni++){
                uint32_t bf[2];
                bf[0] = sBT[t0*132 + n0 + ni*8 + lr];
                bf[1] = sBT[t1*132 + n0 + ni*8 + lr];
                mma_tf32(acc[ni], a, bf);
            }
        }
        float* Sp = g_st + (size_t)id*HD*DS;
        #pragma unroll
        for (int ni = 0; ni < 8; ni++){
            int p = p0 + lr;
            int n = n0 + ni*8 + lc_*2;
            *reinterpret_cast<float2*>(&Sp[(size_t)p*DS + n])     = make_float2(acc[ni][0], acc[ni][1]);
            *reinterpret_cast<float2*>(&Sp[(size_t)(p+8)*DS + n]) = make_float2(acc[ni][2], acc[ni][3]);
        }
    }
}

// ---------------- S2: sequential inter-chunk recurrence; writes prev -------
__global__ void __launch_bounds__(512) s2_rec(){
    __shared__ float sdec[NC];
    int bh = blockIdx.x;            // b*NH + h
    int b = bh / NH, h = bh % NH;
    if (threadIdx.x < NC){
        int id = (b*NC + threadIdx.x)*NH + h;
        sdec[threadIdx.x] = __expf(g_Acs[(size_t)id*Qc + Qc - 1]);
    }
    __syncthreads();
    const size_t stride = (size_t)NH*HD*DS;
    size_t base = ((size_t)(b*NC)*NH + h)*HD*DS;
    for (int e = threadIdx.x; e < HD*DS; e += 512){
        float st[NC];
        #pragma unroll
        for (int c = 0; c < NC; c++) st[c] = g_st[base + c*stride + e];
        float prev = 0.f;
        #pragma unroll
        for (int c = 0; c < NC; c++){
            g_st[base + c*stride + e] = prev;
            prev = sdec[c]*prev + st[c];
        }
    }
}

// ---------------- S3: Y_off (MMA), 2 heads per block sharing the C tile -----
__global__ void __launch_bounds__(256) s3_off(const float* __restrict__ Dp){
    extern __shared__ float sm[];
    uint32_t* sCT  = (uint32_t*)sm;          // Qc*132 tf32(C) [t][n] (shared)
    uint32_t* sPT0 = sCT + Qc*132;           // DS*33  tf32(prev0^T)
    uint32_t* sPT1 = sPT0 + DS*33;           // DS*33  tf32(prev1^T)
    float*    sE0  = (float*)(sPT1 + DS*33); // Qc
    float*    sE1  = sE0 + Qc;               // Qc
    int idp = blockIdx.x;           // ((b*NC + c)*(NH/2) + hp)
    int hp = idp & 7;
    int c  = (idp >> 3) & (NC-1);
    int b  = idp >> 7;
    int h0 = hp*2;
    int id0 = ((b*NC + c)*NH + h0);
    int l0 = c*Qc;
    int tid = threadIdx.x;
    int wid = tid >> 5, lane = tid & 31;
    int lr = lane >> 2, lc_ = lane & 3;

    if (tid < Qc)            sE0[tid]      = __expf(g_Acs[(size_t)id0*Qc + tid]);
    else if (tid < 2*Qc)     sE1[tid - Qc] = __expf(g_Acs[(size_t)(id0+1)*Qc + tid - Qc]);
    // C tile (shared by both heads): Qc*DS floats, 256 threads x 8 float4
    #pragma unroll
    for (int k = 0; k < 8; k++){
        int idx = tid + k*256;
        int t = idx >> 5, c4 = (idx & 31)*4;
        float4 cv = *reinterpret_cast<const float4*>(&g_Cmat[((size_t)b*Ln + l0 + t)*DS + c4]);
        uint4 u;
        u.x = f2tf32(cv.x); u.y = f2tf32(cv.y); u.z = f2tf32(cv.z); u.w = f2tf32(cv.w);
        *reinterpret_cast<uint4*>(&sCT[t*132 + c4]) = u;
    }
    // prev tiles: 4096 floats each, 256 threads x 16
    const float* Sp0 = g_st + (size_t)id0*HD*DS;
    const float* Sp1 = Sp0 + (size_t)HD*DS;
    #pragma unroll
    for (int k = 0; k < 16; k++){
        int idx = tid + k*256;
        int p = idx >> 7, n = idx & 127;
        sPT0[n*33 + p] = f2tf32(Sp0[idx]);
    }
    #pragma unroll
    for (int k = 0; k < 16; k++){
        int idx = tid + k*256;
        int p = idx >> 7, n = idx & 127;
        sPT1[n*33 + p] = f2tf32(Sp1[idx]);
    }
    __syncthreads();

    // warps 0-3 -> head0, warps 4-7 -> head1; each warp: 16 t-rows
    const int wg = wid >> 2;
    const int m0w = (wid & 3)*16;
    const uint32_t* sPT = wg ? sPT1 : sPT0;
    const float*    sE  = wg ? sE1  : sE0;
    const int h = h0 + wg;
    float acc[4][4] = {};
    #pragma unroll
    for (int k = 0; k < 16; k++){
        int ks = k*8;
        uint32_t a[4];
        a[0] = sCT[(m0w+lr)*132   + ks + lc_];
        a[1] = sCT[(m0w+lr+8)*132 + ks + lc_];
        a[2] = sCT[(m0w+lr)*132   + ks + lc_ + 4];
        a[3] = sCT[(m0w+lr+8)*132 + ks + lc_ + 4];
        #pragma unroll
        for (int ni = 0; ni < 4; ni++){
            uint32_t bf[2];
            bf[0] = sPT[(ks+lc_)*33   + ni*8 + lr];
            bf[1] = sPT[(ks+4+lc_)*33 + ni*8 + lr];
            mma_tf32(acc[ni], a, bf);
        }
    }
    float dp = Dp[h];
    #pragma unroll
    for (int ni = 0; ni < 4; ni++){
        int t = m0w + lr;
        int p = ni*8 + lc_*2;
        float e0 = sE[t], e1 = sE[t+8];
        size_t gi  = (((size_t)b*Ln + l0 + t)*NH + h)*HD + p;
        size_t gi2 = gi + (size_t)8*NH*HD;
        float2 y0 = *reinterpret_cast<float2*>(&g_Y[gi]);
        float2 x0 = *reinterpret_cast<const float2*>(&g_xs[gi]);
        y0.x += e0*acc[ni][0] + dp*x0.x;
        y0.y += e0*acc[ni][1] + dp*x0.y;
        *reinterpret_cast<float2*>(&g_Y[gi]) = y0;
        float2 y1 = *reinterpret_cast<float2*>(&g_Y[gi2]);
        float2 x1 = *reinterpret_cast<const float2*>(&g_xs[gi2]);
        y1.x += e1*acc[ni][2] + dp*x1.x;
        y1.y += e1*acc[ni][3] + dp*x1.y;
        *reinterpret_cast<float2*>(&g_Y[gi2]) = y1;
    }
}

// ---------------- K4: gate with SiLU(z) + RMSNorm over 512 (float4) --------
__global__ void __launch_bounds__(128) k4_gate(const float* __restrict__ rms_w){
    __shared__ float red[4];
    __shared__ float s_r;
    int bl = blockIdx.x;
    int tid = threadIdx.x;
    float4 z4 = *reinterpret_cast<const float4*>(&g_zx[(size_t)bl*DIP + tid*4]);
    float4 y4 = *reinterpret_cast<const float4*>(&g_Y[(size_t)bl*DI + tid*4]);
    float4 v4;
    v4.x = y4.x * fsilu(z4.x);
    v4.y = y4.y * fsilu(z4.y);
    v4.z = y4.z * fsilu(z4.z);
    v4.w = y4.w * fsilu(z4.w);
    float ss = v4.x*v4.x + v4.y*v4.y + v4.z*v4.z + v4.w*v4.w;
    #pragma unroll
    for (int o = 16; o; o >>= 1) ss += __shfl_xor_sync(~0u, ss, o);
    if ((tid & 31) == 0) red[tid >> 5] = ss;
    __syncthreads();
    if (tid == 0){
        float t = red[0] + red[1] + red[2] + red[3];
        s_r = rsqrtf(t/512.f + 1e-5f);
    }
    __syncthreads();
    float r = s_r;
    float4 w4 = *reinterpret_cast<const float4*>(&rms_w[tid*4]);
    v4.x *= r*w4.x; v4.y *= r*w4.y; v4.z *= r*w4.z; v4.w *= r*w4.w;
    *reinterpret_cast<float4*>(&g_yf[(size_t)bl*DI + tid*4]) = v4;
}

// ---------------- K5: out-proj GEMM, 64(M)x128(N) tiles, 256 blocks --------
// op[b,n,l] = sum_k yf[m,k]*Wout[n,k]; epilogue emits GroupNorm partials.
__global__ void __launch_bounds__(256) k5_mma(const float* __restrict__ Wout){
    __shared__ uint32_t As[2][16][68];    // [k][m] 64+pad
    __shared__ uint32_t Bs[2][16][132];   // [k][n] 128+pad
    __shared__ float s_part[8][2];
    const int n0 = blockIdx.x * 128;
    const int m0 = blockIdx.y * 64;
    const int tid = threadIdx.x;
    const int wid = tid >> 5, lane = tid & 31;
    const int wm = wid >> 2, wn = wid & 3;    // warp tile 32(m) x 32(n)
    const int lr = lane >> 2, lc = lane & 3;
    float acc[2][4][4] = {};

    const int a_m = tid & 63, a_k = tid >> 6;    // A: float4 along k
    const int t_i = tid & 127, t_kq = tid >> 7;  // B: as before

    {
        float4 va = *reinterpret_cast<const float4*>(&g_yf[(size_t)(m0 + a_m)*DI + a_k*4]);
        As[0][a_k*4+0][a_m]=f2tf32(va.x);
        As[0][a_k*4+1][a_m]=f2tf32(va.y);
        As[0][a_k*4+2][a_m]=f2tf32(va.z);
        As[0][a_k*4+3][a_m]=f2tf32(va.w);
    }
    #pragma unroll
    for (int i = 0; i < 2; i++){
        int kq = t_kq + i*2;
        float4 vb = *reinterpret_cast<const float4*>(&Wout[(size_t)(n0 + t_i)*DI + kq*4]);
        Bs[0][kq*4+0][t_i]=f2tf32(vb.x);
        Bs[0][kq*4+1][t_i]=f2tf32(vb.y);
        Bs[0][kq*4+2][t_i]=f2tf32(vb.z);
        Bs[0][kq*4+3][t_i]=f2tf32(vb.w);
    }
    __syncthreads();

    for (int s = 0; s < 32; s++){
        int buf = s & 1;
        float4 av, bv[2];
        if (s < 31){
            int c0 = (s+1)*16;
            av = *reinterpret_cast<const float4*>(&g_yf[(size_t)(m0 + a_m)*DI + c0 + a_k*4]);
            #pragma unroll
            for (int i = 0; i < 2; i++){
                int kq = t_kq + i*2;
                bv[i] = *reinterpret_cast<const float4*>(&Wout[(size_t)(n0 + t_i)*DI + c0 + kq*4]);
            }
        }
        #pragma unroll
        for (int ksub = 0; ksub < 2; ksub++){
            int ks = ksub*8;
            uint32_t af[2][4], bf[4][2];
            #pragma unroll
            for (int mi = 0; mi < 2; mi++){
                int mr = wm*32 + mi*16 + lr;
                af[mi][0] = As[buf][ks+lc][mr];
                af[mi][1] = As[buf][ks+lc][mr+8];
                af[mi][2] = As[buf][ks+4+lc][mr];
                af[mi][3] = As[buf][ks+4+lc][mr+8];
            }
            #pragma unroll
            for (int ni = 0; ni < 4; ni++){
                int nc = wn*32 + ni*8 + lr;
                bf[ni][0] = Bs[buf][ks+lc][nc];
                bf[ni][1] = Bs[buf][ks+4+lc][nc];
            }
            #pragma unroll
            for (int mi = 0; mi < 2; mi++)
                #pragma unroll
                for (int ni = 0; ni < 4; ni++)
                    mma_tf32(acc[mi][ni], af[mi], bf[ni]);
        }
        if (s < 31){
            As[buf^1][a_k*4+0][a_m]=f2tf32(av.x);
            As[buf^1][a_k*4+1][a_m]=f2tf32(av.y);
            As[buf^1][a_k*4+2][a_m]=f2tf32(av.z);
            As[buf^1][a_k*4+3][a_m]=f2tf32(av.w);
            #pragma unroll
            for (int i = 0; i < 2; i++){
                int kq = t_kq + i*2;
                Bs[buf^1][kq*4+0][t_i]=f2tf32(bv[i].x);
                Bs[buf^1][kq*4+1][t_i]=f2tf32(bv[i].y);
                Bs[buf^1][kq*4+2][t_i]=f2tf32(bv[i].z);
                Bs[buf^1][kq*4+3][t_i]=f2tf32(bv[i].w);
            }
            __syncthreads();
        }
    }
    // store transposed + accumulate GroupNorm partials
    float psum = 0.f, psq = 0.f;
    #pragma unroll
    for (int mi = 0; mi < 2; mi++){
        int m = m0 + wm*32 + mi*16 + lr;
        int bb = m >> 10, l = m & 1023;
        #pragma unroll
        for (int ni = 0; ni < 4; ni++){
            int n = n0 + wn*32 + ni*8 + lc*2;
            g_op[((size_t)bb*DM + n  )*Ln + l    ] = acc[mi][ni][0];
            g_op[((size_t)bb*DM + n+1)*Ln + l    ] = acc[mi][ni][1];
            g_op[((size_t)bb*DM + n  )*Ln + l + 8] = acc[mi][ni][2];
            g_op[((size_t)bb*DM + n+1)*Ln + l + 8] = acc[mi][ni][3];
            #pragma unroll
            for (int q = 0; q < 4; q++){
                float vv = acc[mi][ni][q];
                psum += vv; psq += vv*vv;
            }
        }
    }
    #pragma unroll
    for (int o = 16; o; o >>= 1){
        psum += __shfl_xor_sync(~0u, psum, o);
        psq  += __shfl_xor_sync(~0u, psq,  o);
    }
    if (lane == 0){ s_part[wid][0] = psum; s_part[wid][1] = psq; }
    __syncthreads();
    if (tid < 4){
        int g = blockIdx.x*4 + tid;          // global group 0..7
        int b = blockIdx.y >> 4, by = blockIdx.y & 15;
        float S  = s_part[tid][0] + s_part[tid+4][0];
        float S2 = s_part[tid][1] + s_part[tid+4][1];
        int slot = ((b*8 + g)*16 + by)*2;
        g_gnpart[slot]   = S;
        g_gnpart[slot+1] = S2;
    }
}

// ---------------- K7: GN finalize + normalize + affine + Mish (float4) -----
__global__ void __launch_bounds__(256) k7_mish(const float* __restrict__ gn_w,
                        const float* __restrict__ gn_b,
                        float* __restrict__ out){
    __shared__ float s_mu, s_rstd;
    int blk = blockIdx.x;            // b*DM + m
    int b = blk >> 8, m = blk & 255;
    int g = m >> 5;
    if (threadIdx.x == 0){
        double S = 0.0, S2 = 0.0;
        int base = ((b*8 + g)*16)*2;
        #pragma unroll
        for (int by = 0; by < 16; by++){
            S  += (double)g_gnpart[base + by*2];
            S2 += (double)g_gnpart[base + by*2 + 1];
        }
        double N = 32.0*Ln;
        double mu  = S / N;
        double var = S2 / N - mu*mu;
        s_mu   = (float)mu;
        s_rstd = rsqrtf((float)var + 1e-5f);
    }
    __syncthreads();
    float mu = s_mu, r = s_rstd;
    float w = gn_w[m], bo = gn_b[m];
    float4 v4 = *reinterpret_cast<const float4*>(&g_op[(size_t)blk*Ln + threadIdx.x*4]);
    v4.x = fmish((v4.x - mu)*r*w + bo);
    v4.y = fmish((v4.y - mu)*r*w + bo);
    v4.z = fmish((v4.z - mu)*r*w + bo);
    v4.w = fmish((v4.w - mu)*r*w + bo);
    *reinterpret_cast<float4*>(&out[(size_t)blk*Ln + threadIdx.x*4]) = v4;
}

// ---------------------------------------------------------------------------
extern "C" void kernel_launch(void* const* d_in, const int* in_sizes, int n_in,
                              void* d_out, int out_size){
    const float* x       = (const float*)d_in[0];
    const float* W_in    = (const float*)d_in[1];
    const float* conv_w  = (const float*)d_in[2];
    const float* conv_b  = (const float*)d_in[3];
    const float* dt_bias = (const float*)d_in[4];
    const float* A_log   = (const float*)d_in[5];
    const float* Dp      = (const float*)d_in[6];
    const float* rms_w   = (const float*)d_in[7];
    const float* W_out   = (const float*)d_in[8];
    const float* gn_w    = (const float*)d_in[9];
    const float* gn_b    = (const float*)d_in[10];
    float* out = (float*)d_out;

    const int S1_SMEM = (Qc*36*2 + Qc*132 + Qc*68 + Qc*2) * 4;        // ~68.6 KB
    const int S3_SMEM = (Qc*132 + 2*DS*33 + 2*Qc) * 4;                // ~68.1 KB
    cudaFuncSetAttribute(s1_intra, cudaFuncAttributeMaxDynamicSharedMemorySize, S1_SMEM);
    cudaFuncSetAttribute(s3_off,   cudaFuncAttributeMaxDynamicSharedMemorySize, S3_SMEM);

    k1_mma<<<dim3((DIP + 127)/128, (Bn*Ln)/128), 256>>>(x, W_in);
    k2_conv<<<dim3(Ln/4, Bn), 224>>>(conv_w, conv_b, dt_bias);
    s0_gram<<<Bn*NC, 256>>>();
    s1_intra<<<Bn*NC*NH, 256, S1_SMEM>>>(A_log);
    s2_rec<<<Bn*NH, 512>>>();
    s3_off<<<Bn*NC*(NH/2), 256, S3_SMEM>>>(Dp);
    k4_gate<<<Bn*Ln, 128>>>(rms_w);
    k5_mma<<<dim3(DM/128, (Bn*Ln)/64), 256>>>(W_out);
    k7_mish<<<Bn*DM, 256>>>(gn_w, gn_b, out);
}

// round 17
// speedup vs baseline: 1.0480x; 1.0480x over previous
#include <cuda_runtime.h>
#include <math.h>
#include <stdint.h>

#define Bn 8
#define Ln 1024
#define DM 256
#define DI 512
#define NH 16
#define HD 32
#define DS 128
#define CONVD 768
#define DIP 1296
#define Qc 64
#define NC 16   /* Ln/Qc */

// ---------------- scratch (device globals; no mallocs allowed) ----------------
__device__ float g_zx[Bn*Ln*DIP];       // in-proj output
__device__ float g_xs[Bn*Ln*DI];        // conv output, x part (raw, no dt)
__device__ float g_Bmat[Bn*Ln*DS];
__device__ float g_Cmat[Bn*Ln*DS];
__device__ float g_dt[Bn*Ln*NH];
__device__ float g_G[Bn*NC*Qc*Qc];      // TRANSPOSED Gram: Gt[s][t] = C[t]·B[s]
__device__ float g_Acs[Bn*NC*NH*Qc];    // per-chunk inclusive cumsum of dA
__device__ float g_Y[Bn*Ln*DI];         // SSD output accumulator
__device__ float g_st[Bn*NC*NH*HD*DS];  // chunk states -> then prev states
__device__ float g_yf[Bn*Ln*DI];        // gated + rmsnormed
__device__ float g_op[Bn*DM*Ln];        // out-proj, already transposed (b,m,l)
__device__ float g_gnpart[Bn*8*8*2];    // per-(b,g,by) partial sum/sumsq from k5

// ---------------- fast math helpers -----------------------------------------
__device__ __forceinline__ float fsilu(float x){
    return __fdividef(x, 1.f + __expf(-x));
}
__device__ __forceinline__ float fmish(float v){
    float t = 1.f + __expf(v);
    return v - v * __fdividef(2.f, t*t + 1.f);
}

// ---------------- tf32 mma helpers -----------------------------------------
__device__ __forceinline__ uint32_t f2tf32(float f){
    uint32_t r; asm("cvt.rna.tf32.f32 %0, %1;" : "=r"(r) : "f"(f)); return r;
}
__device__ __forceinline__ void mma_tf32(float* c, const uint32_t* a, const uint32_t* b){
    asm volatile("mma.sync.aligned.m16n8k8.row.col.f32.tf32.tf32.f32 "
        "{%0,%1,%2,%3}, {%4,%5,%6,%7}, {%8,%9}, {%0,%1,%2,%3};\n"
        : "+f"(c[0]), "+f"(c[1]), "+f"(c[2]), "+f"(c[3])
        : "r"(a[0]), "r"(a[1]), "r"(a[2]), "r"(a[3]),
          "r"(b[0]), "r"(b[1]));
}

// ---------------- K1: in-proj GEMM via tf32 MMA ----------------------------
// zx[m,n] = sum_c x[b,c,l] * W_in[n,c];  m=(b,l): M=8192, N=1296, K=256
__global__ void __launch_bounds__(256) k1_mma(const float* __restrict__ x,
                                              const float* __restrict__ W){
    __shared__ uint32_t As[2][16][132];   // [k][m]
    __shared__ uint32_t Bs[2][16][132];   // [k][n]
    const int n0 = blockIdx.x * 128;
    const int m0 = blockIdx.y * 128;
    const int b  = m0 >> 10;
    const int l0 = m0 & 1023;
    const int tid = threadIdx.x;
    const int wid = tid >> 5, lane = tid & 31;
    const int wm = wid >> 2, wn = wid & 3;      // warp grid 2(m) x 4(n)
    const int lr = lane >> 2, lc = lane & 3;
    float acc[4][4][4] = {};

    const int a_kk = tid >> 5;
    const int a_mm = (tid & 31) << 2;
    const int b_n  = tid & 127;
    const int b_kq = tid >> 7;
    const int n_glob = n0 + b_n;

    #pragma unroll
    for (int i = 0; i < 2; i++){
        int kk = a_kk + i*8;
        float4 v = *reinterpret_cast<const float4*>(&x[((size_t)b*DM + kk)*Ln + l0 + a_mm]);
        uint32_t* p = &As[0][kk][a_mm];
        p[0]=f2tf32(v.x); p[1]=f2tf32(v.y); p[2]=f2tf32(v.z); p[3]=f2tf32(v.w);
    }
    #pragma unroll
    for (int i = 0; i < 2; i++){
        int kq = b_kq + i*2;
        float4 v = make_float4(0.f,0.f,0.f,0.f);
        if (n_glob < DIP) v = *reinterpret_cast<const float4*>(&W[(size_t)n_glob*DM + kq*4]);
        Bs[0][kq*4+0][b_n]=f2tf32(v.x);
        Bs[0][kq*4+1][b_n]=f2tf32(v.y);
        Bs[0][kq*4+2][b_n]=f2tf32(v.z);
        Bs[0][kq*4+3][b_n]=f2tf32(v.w);
    }
    __syncthreads();

    for (int s = 0; s < 16; s++){
        int buf = s & 1;
        float4 av[2], bv[2];
        if (s < 15){
            int c0 = (s+1)*16;
            #pragma unroll
            for (int i = 0; i < 2; i++){
                int kk = a_kk + i*8;
                av[i] = *reinterpret_cast<const float4*>(&x[((size_t)b*DM + c0 + kk)*Ln + l0 + a_mm]);
            }
            #pragma unroll
            for (int i = 0; i < 2; i++){
                int kq = b_kq + i*2;
                bv[i] = (n_glob < DIP)
                    ? *reinterpret_cast<const float4*>(&W[(size_t)n_glob*DM + c0 + kq*4])
                    : make_float4(0.f,0.f,0.f,0.f);
            }
        }
        #pragma unroll
        for (int ksub = 0; ksub < 2; ksub++){
            int ks = ksub*8;
            uint32_t af[4][4], bf[4][2];
            #pragma unroll
            for (int mi = 0; mi < 4; mi++){
                int mr = wm*64 + mi*16 + lr;
                af[mi][0] = As[buf][ks+lc][mr];
                af[mi][1] = As[buf][ks+lc][mr+8];
                af[mi][2] = As[buf][ks+4+lc][mr];
                af[mi][3] = As[buf][ks+4+lc][mr+8];
            }
            #pragma unroll
            for (int ni = 0; ni < 4; ni++){
                int nc = wn*32 + ni*8 + lr;
                bf[ni][0] = Bs[buf][ks+lc][nc];
                bf[ni][1] = Bs[buf][ks+4+lc][nc];
            }
            #pragma unroll
            for (int mi = 0; mi < 4; mi++)
                #pragma unroll
                for (int ni = 0; ni < 4; ni++)
                    mma_tf32(acc[mi][ni], af[mi], bf[ni]);
        }
        if (s < 15){
            #pragma unroll
            for (int i = 0; i < 2; i++){
                int kk = a_kk + i*8;
                uint32_t* p = &As[buf^1][kk][a_mm];
                p[0]=f2tf32(av[i].x); p[1]=f2tf32(av[i].y); p[2]=f2tf32(av[i].z); p[3]=f2tf32(av[i].w);
            }
            #pragma unroll
            for (int i = 0; i < 2; i++){
                int kq = b_kq + i*2;
                Bs[buf^1][kq*4+0][b_n]=f2tf32(bv[i].x);
                Bs[buf^1][kq*4+1][b_n]=f2tf32(bv[i].y);
                Bs[buf^1][kq*4+2][b_n]=f2tf32(bv[i].z);
                Bs[buf^1][kq*4+3][b_n]=f2tf32(bv[i].w);
            }
            __syncthreads();
        }
    }
    #pragma unroll
    for (int mi = 0; mi < 4; mi++){
        int m = m0 + wm*64 + mi*16 + lr;
        #pragma unroll
        for (int ni = 0; ni < 4; ni++){
            int n = n0 + wn*32 + ni*8 + lc*2;
            if (n < DIP){
                g_zx[(size_t)m*DIP + n]       = acc[mi][ni][0];
                g_zx[(size_t)m*DIP + n + 1]   = acc[mi][ni][1];
                g_zx[(size_t)(m+8)*DIP + n]   = acc[mi][ni][2];
                g_zx[(size_t)(m+8)*DIP + n+1] = acc[mi][ni][3];
            }
        }
    }
}

// ---------------- K2: depthwise conv + SiLU + split, and dt=softplus -------
__global__ void __launch_bounds__(224) k2_conv(const float* __restrict__ conv_w,
                        const float* __restrict__ conv_b,
                        const float* __restrict__ dt_bias){
    int tid = threadIdx.x;
    int l0 = blockIdx.x*4, b = blockIdx.y;
    if (tid < 192){
        int ch = tid*4;
        float4 cw0 = *reinterpret_cast<const float4*>(conv_w + (ch+0)*4);
        float4 cw1 = *reinterpret_cast<const float4*>(conv_w + (ch+1)*4);
        float4 cw2 = *reinterpret_cast<const float4*>(conv_w + (ch+2)*4);
        float4 cw3 = *reinterpret_cast<const float4*>(conv_w + (ch+3)*4);
        float4 bias = *reinterpret_cast<const float4*>(conv_b + ch);
        float4 v[7];
        #pragma unroll
        for (int k = 0; k < 7; k++){
            int ls = l0 - 3 + k;
            v[k] = (ls >= 0)
                ? *reinterpret_cast<const float4*>(&g_zx[((size_t)b*Ln + ls)*DIP + DI + ch])
                : make_float4(0.f,0.f,0.f,0.f);
        }
        #pragma unroll
        for (int j = 0; j < 4; j++){
            float4 r;
            r.x = fsilu(bias.x + cw0.x*v[j].x + cw0.y*v[j+1].x + cw0.z*v[j+2].x + cw0.w*v[j+3].x);
            r.y = fsilu(bias.y + cw1.x*v[j].y + cw1.y*v[j+1].y + cw1.z*v[j+2].y + cw1.w*v[j+3].y);
            r.z = fsilu(bias.z + cw2.x*v[j].z + cw2.y*v[j+1].z + cw2.z*v[j+2].z + cw2.w*v[j+3].z);
            r.w = fsilu(bias.w + cw3.x*v[j].w + cw3.y*v[j+1].w + cw3.z*v[j+2].w + cw3.w*v[j+3].w);
            size_t row = (size_t)b*Ln + l0 + j;
            if (ch < DI)
                *reinterpret_cast<float4*>(&g_xs[row*DI + ch]) = r;
            else if (ch < DI+DS)
                *reinterpret_cast<float4*>(&g_Bmat[row*DS + (ch-DI)]) = r;
            else
                *reinterpret_cast<float4*>(&g_Cmat[row*DS + (ch-DI-DS)]) = r;
        }
    } else if (tid < 192 + NH){
        int hh = tid - 192;
        float db = dt_bias[hh];
        #pragma unroll
        for (int j = 0; j < 4; j++){
            size_t row = (size_t)b*Ln + l0 + j;
            float v = g_zx[row*DIP + DI + CONVD + hh] + db;
            float sp = (v > 20.f) ? v : log1pf(__expf(v));
            g_dt[row*NH + hh] = sp;
        }
    }
}

// ---------------- S0: Gram Gt[b,c,s,t] = C[t]·B[s] (stored transposed) ------
__global__ void s0_gram(){
    __shared__ float Cs[32][65];
    __shared__ float Bs[32][65];
    int bc = blockIdx.x;            // b*NC + c
    int b = bc / NC, c = bc % NC;
    int l0 = c*Qc;
    int tid = threadIdx.x;
    int tx = tid & 15, ty = tid >> 4;
    float acc[4][4] = {};
    for (int n0 = 0; n0 < DS; n0 += 32){
        #pragma unroll
        for (int k = 0; k < 8; k++){
            int idx = tid + k*256;
            int t = idx >> 5, kk = idx & 31;
            Cs[kk][t] = g_Cmat[((size_t)b*Ln + l0 + t)*DS + n0 + kk];
            Bs[kk][t] = g_Bmat[((size_t)b*Ln + l0 + t)*DS + n0 + kk];
        }
        __syncthreads();
        #pragma unroll
        for (int kk = 0; kk < 32; kk++){
            float a[4], bb[4];
            #pragma unroll
            for (int i = 0; i < 4; i++) a[i]  = Bs[kk][ty*4+i];   // rows = s
            #pragma unroll
            for (int j = 0; j < 4; j++) bb[j] = Cs[kk][tx*4+j];   // cols = t
            #pragma unroll
            for (int i = 0; i < 4; i++)
                #pragma unroll
                for (int j = 0; j < 4; j++) acc[i][j] += a[i]*bb[j];
        }
        __syncthreads();
    }
    #pragma unroll
    for (int i = 0; i < 4; i++)
        #pragma unroll
        for (int j = 0; j < 4; j++)
            g_G[((size_t)bc*Qc + ty*4 + i)*Qc + tx*4 + j] = acc[i][j];
}

// ---------------- S1: per (b,chunk,head): scan, Y_diag(MMA), states(MMA) ----
// Single-warp pair-scan, all global loads issued at entry, 2 barriers total.
__global__ void __launch_bounds__(256) s1_intra(const float* __restrict__ A_log){
    extern __shared__ float sm[];
    uint32_t* sXT  = (uint32_t*)sm;              // Qc*36  tf32(X*dt)
    uint32_t* sXS  = sXT + Qc*36;                // Qc*36  tf32(X*dt*Se)
    uint32_t* sBT  = sXS + Qc*36;                // Qc*132 tf32(B)
    uint32_t* sWT  = sBT + Qc*132;               // Qc*68  tf32(W^T)
    float*    sAcs = (float*)(sWT + Qc*68);      // Qc
    float*    sdt  = sAcs + Qc;                  // Qc
    int id = blockIdx.x;            // ((b*NC + c)*NH + h)
    int h = id % NH;
    int c = (id / NH) % NC;
    int b = id / (NH*NC);
    int l0 = c*Qc;
    int tid = threadIdx.x;
    int wid = tid >> 5, lane = tid & 31;
    int lr = lane >> 2, lc_ = lane & 3;

    const float* Gt = g_G + ((size_t)(b*NC + c)*Qc)*Qc;
    float gv[16];
    #pragma unroll
    for (int k = 0; k < 16; k++){
        int idx = tid + k*256;
        int s_ = idx >> 6, t_ = idx & 63;
        gv[k] = (s_ <= t_) ? Gt[s_*Qc + t_] : 0.f;
    }
    float4 xv[2];
    #pragma unroll
    for (int k = 0; k < 2; k++){
        int idx4 = tid + k*256;
        int t = idx4 >> 3, p4 = (idx4 & 7)*4;
        xv[k] = *reinterpret_cast<const float4*>(&g_xs[(((size_t)b*Ln + l0 + t)*NH + h)*HD + p4]);
    }
    #pragma unroll
    for (int k = 0; k < 8; k++){
        int idx = tid + k*256;
        int t = idx >> 5, c4 = (idx & 31)*4;
        float4 bv = *reinterpret_cast<const float4*>(&g_Bmat[((size_t)b*Ln + l0 + t)*DS + c4]);
        uint4 u;
        u.x = f2tf32(bv.x); u.y = f2tf32(bv.y); u.z = f2tf32(bv.z); u.w = f2tf32(bv.w);
        *reinterpret_cast<uint4*>(&sBT[t*132 + c4]) = u;
    }
    if (tid < 32){
        int t0 = 2*tid, t1 = 2*tid + 1;
        float d0 = g_dt[((size_t)b*Ln + l0 + t0)*NH + h];
        float d1 = g_dt[((size_t)b*Ln + l0 + t1)*NH + h];
        sdt[t0] = d0; sdt[t1] = d1;
        float mA = -__expf(A_log[h]);
        float a0 = d0*mA, a1 = d1*mA;
        float ps = a0 + a1;
        #pragma unroll
        for (int off = 1; off < 32; off <<= 1){
            float u = __shfl_up_sync(0xffffffffu, ps, off);
            if (tid >= off) ps += u;
        }
        float acs1 = ps;
        float acs0 = ps - a1;
        sAcs[t0] = acs0; sAcs[t1] = acs1;
        g_Acs[(size_t)id*Qc + t0] = acs0;
        g_Acs[(size_t)id*Qc + t1] = acs1;
    }
    __syncthreads();

    float tot = sAcs[Qc-1];
    #pragma unroll
    for (int k = 0; k < 2; k++){
        int idx4 = tid + k*256;
        int t = idx4 >> 3, p4 = (idx4 & 7)*4;
        float d = sdt[t];
        float se = __expf(tot - sAcs[t]);
        float x0 = xv[k].x*d, x1 = xv[k].y*d, x2 = xv[k].z*d, x3 = xv[k].w*d;
        uint4 u1, u2;
        u1.x = f2tf32(x0); u1.y = f2tf32(x1); u1.z = f2tf32(x2); u1.w = f2tf32(x3);
        u2.x = f2tf32(x0*se); u2.y = f2tf32(x1*se); u2.z = f2tf32(x2*se); u2.w = f2tf32(x3*se);
        *reinterpret_cast<uint4*>(&sXT[t*36 + p4]) = u1;
        *reinterpret_cast<uint4*>(&sXS[t*36 + p4]) = u2;
    }
    #pragma unroll
    for (int k = 0; k < 16; k++){
        int idx = tid + k*256;
        int s_ = idx >> 6, t_ = idx & 63;
        float w = 0.f;
        if (s_ <= t_) w = gv[k] * __expf(sAcs[t_] - sAcs[s_]);
        sWT[s_*68 + t_] = f2tf32(w);
    }
    __syncthreads();

    if (wid < 4){
        const int m0w = wid*16;
        float acc[4][4] = {};
        const int kmax = 2*(wid+1);   // triangular
        for (int k = 0; k < kmax; k++){
            int ks = k*8;
            uint32_t a[4];
            a[0] = sWT[(ks+lc_)*68   + m0w + lr];
            a[1] = sWT[(ks+lc_)*68   + m0w + lr + 8];
            a[2] = sWT[(ks+4+lc_)*68 + m0w + lr];
            a[3] = sWT[(ks+4+lc_)*68 + m0w + lr + 8];
            #pragma unroll
            for (int ni = 0; ni < 4; ni++){
                uint32_t bf[2];
                bf[0] = sXT[(ks+lc_)*36   + ni*8 + lr];
                bf[1] = sXT[(ks+4+lc_)*36 + ni*8 + lr];
                mma_tf32(acc[ni], a, bf);
            }
        }
        #pragma unroll
        for (int ni = 0; ni < 4; ni++){
            int t = m0w + lr;
            int p = ni*8 + lc_*2;
            size_t gi = (((size_t)b*Ln + l0 + t)*NH + h)*HD + p;
            *reinterpret_cast<float2*>(&g_Y[gi]) = make_float2(acc[ni][0], acc[ni][1]);
            size_t gi2 = gi + (size_t)8*NH*HD;
            *reinterpret_cast<float2*>(&g_Y[gi2]) = make_float2(acc[ni][2], acc[ni][3]);
        }
    } else {
        const int ww = wid - 4;
        const int p0 = (ww & 1)*16, n0 = (ww >> 1)*64;
        float acc[8][4] = {};
        #pragma unroll
        for (int k = 0; k < 8; k++){
            int ks = k*8;
            int t0 = ks + lc_, t1 = ks + 4 + lc_;
            uint32_t a[4];
            a[0] = sXS[t0*36 + p0 + lr];
            a[1] = sXS[t0*36 + p0 + lr + 8];
            a[2] = sXS[t1*36 + p0 + lr];
            a[3] = sXS[t1*36 + p0 + lr + 8];
            #pragma unroll
            for (int ni = 0; ni < 8; ni++){
                uint32_t bf[2];
                bf[0] = sBT[t0*132 + n0 + ni*8 + lr];
                bf[1] = sBT[t1*132 + n0 + ni*8 + lr];
                mma_tf32(acc[ni], a, bf);
            }
        }
        float* Sp = g_st + (size_t)id*HD*DS;
        #pragma unroll
        for (int ni = 0; ni < 8; ni++){
            int p = p0 + lr;
            int n = n0 + ni*8 + lc_*2;
            *reinterpret_cast<float2*>(&Sp[(size_t)p*DS + n])     = make_float2(acc[ni][0], acc[ni][1]);
            *reinterpret_cast<float2*>(&Sp[(size_t)(p+8)*DS + n]) = make_float2(acc[ni][2], acc[ni][3]);
        }
    }
}

// ---------------- S2: sequential inter-chunk recurrence; writes prev -------
__global__ void __launch_bounds__(512) s2_rec(){
    __shared__ float sdec[NC];
    int bh = blockIdx.x;            // b*NH + h
    int b = bh / NH, h = bh % NH;
    if (threadIdx.x < NC){
        int id = (b*NC + threadIdx.x)*NH + h;
        sdec[threadIdx.x] = __expf(g_Acs[(size_t)id*Qc + Qc - 1]);
    }
    __syncthreads();
    const size_t stride = (size_t)NH*HD*DS;
    size_t base = ((size_t)(b*NC)*NH + h)*HD*DS;
    for (int e = threadIdx.x; e < HD*DS; e += 512){
        float st[NC];
        #pragma unroll
        for (int c = 0; c < NC; c++) st[c] = g_st[base + c*stride + e];
        float prev = 0.f;
        #pragma unroll
        for (int c = 0; c < NC; c++){
            g_st[base + c*stride + e] = prev;
            prev = sdec[c]*prev + st[c];
        }
    }
}

// ---------------- S3: Y_off (MMA), 2 heads per block sharing the C tile -----
__global__ void __launch_bounds__(256) s3_off(const float* __restrict__ Dp){
    extern __shared__ float sm[];
    uint32_t* sCT  = (uint32_t*)sm;          // Qc*132 tf32(C) [t][n] (shared)
    uint32_t* sPT0 = sCT + Qc*132;           // DS*33  tf32(prev0^T)
    uint32_t* sPT1 = sPT0 + DS*33;           // DS*33  tf32(prev1^T)
    float*    sE0  = (float*)(sPT1 + DS*33); // Qc
    float*    sE1  = sE0 + Qc;               // Qc
    int idp = blockIdx.x;           // ((b*NC + c)*(NH/2) + hp)
    int hp = idp & 7;
    int c  = (idp >> 3) & (NC-1);
    int b  = idp >> 7;
    int h0 = hp*2;
    int id0 = ((b*NC + c)*NH + h0);
    int l0 = c*Qc;
    int tid = threadIdx.x;
    int wid = tid >> 5, lane = tid & 31;
    int lr = lane >> 2, lc_ = lane & 3;

    if (tid < Qc)            sE0[tid]      = __expf(g_Acs[(size_t)id0*Qc + tid]);
    else if (tid < 2*Qc)     sE1[tid - Qc] = __expf(g_Acs[(size_t)(id0+1)*Qc + tid - Qc]);
    #pragma unroll
    for (int k = 0; k < 8; k++){
        int idx = tid + k*256;
        int t = idx >> 5, c4 = (idx & 31)*4;
        float4 cv = *reinterpret_cast<const float4*>(&g_Cmat[((size_t)b*Ln + l0 + t)*DS + c4]);
        uint4 u;
        u.x = f2tf32(cv.x); u.y = f2tf32(cv.y); u.z = f2tf32(cv.z); u.w = f2tf32(cv.w);
        *reinterpret_cast<uint4*>(&sCT[t*132 + c4]) = u;
    }
    const float* Sp0 = g_st + (size_t)id0*HD*DS;
    const float* Sp1 = Sp0 + (size_t)HD*DS;
    #pragma unroll
    for (int k = 0; k < 16; k++){
        int idx = tid + k*256;
        int p = idx >> 7, n = idx & 127;
        sPT0[n*33 + p] = f2tf32(Sp0[idx]);
    }
    #pragma unroll
    for (int k = 0; k < 16; k++){
        int idx = tid + k*256;
        int p = idx >> 7, n = idx & 127;
        sPT1[n*33 + p] = f2tf32(Sp1[idx]);
    }
    __syncthreads();

    const int wg = wid >> 2;
    const int m0w = (wid & 3)*16;
    const uint32_t* sPT = wg ? sPT1 : sPT0;
    const float*    sE  = wg ? sE1  : sE0;
    const int h = h0 + wg;
    float acc[4][4] = {};
    #pragma unroll
    for (int k = 0; k < 16; k++){
        int ks = k*8;
        uint32_t a[4];
        a[0] = sCT[(m0w+lr)*132   + ks + lc_];
        a[1] = sCT[(m0w+lr+8)*132 + ks + lc_];
        a[2] = sCT[(m0w+lr)*132   + ks + lc_ + 4];
        a[3] = sCT[(m0w+lr+8)*132 + ks + lc_ + 4];
        #pragma unroll
        for (int ni = 0; ni < 4; ni++){
            uint32_t bf[2];
            bf[0] = sPT[(ks+lc_)*33   + ni*8 + lr];
            bf[1] = sPT[(ks+4+lc_)*33 + ni*8 + lr];
            mma_tf32(acc[ni], a, bf);
        }
    }
    float dp = Dp[h];
    #pragma unroll
    for (int ni = 0; ni < 4; ni++){
        int t = m0w + lr;
        int p = ni*8 + lc_*2;
        float e0 = sE[t], e1 = sE[t+8];
        size_t gi  = (((size_t)b*Ln + l0 + t)*NH + h)*HD + p;
        size_t gi2 = gi + (size_t)8*NH*HD;
        float2 y0 = *reinterpret_cast<float2*>(&g_Y[gi]);
        float2 x0 = *reinterpret_cast<const float2*>(&g_xs[gi]);
        y0.x += e0*acc[ni][0] + dp*x0.x;
        y0.y += e0*acc[ni][1] + dp*x0.y;
        *reinterpret_cast<float2*>(&g_Y[gi]) = y0;
        float2 y1 = *reinterpret_cast<float2*>(&g_Y[gi2]);
        float2 x1 = *reinterpret_cast<const float2*>(&g_xs[gi2]);
        y1.x += e1*acc[ni][2] + dp*x1.x;
        y1.y += e1*acc[ni][3] + dp*x1.y;
        *reinterpret_cast<float2*>(&g_Y[gi2]) = y1;
    }
}

// ---------------- K4: gate with SiLU(z) + RMSNorm over 512 (float4) --------
__global__ void __launch_bounds__(128) k4_gate(const float* __restrict__ rms_w){
    __shared__ float red[4];
    __shared__ float s_r;
    int bl = blockIdx.x;
    int tid = threadIdx.x;
    float4 z4 = *reinterpret_cast<const float4*>(&g_zx[(size_t)bl*DIP + tid*4]);
    float4 y4 = *reinterpret_cast<const float4*>(&g_Y[(size_t)bl*DI + tid*4]);
    float4 v4;
    v4.x = y4.x * fsilu(z4.x);
    v4.y = y4.y * fsilu(z4.y);
    v4.z = y4.z * fsilu(z4.z);
    v4.w = y4.w * fsilu(z4.w);
    float ss = v4.x*v4.x + v4.y*v4.y + v4.z*v4.z + v4.w*v4.w;
    #pragma unroll
    for (int o = 16; o; o >>= 1) ss += __shfl_xor_sync(~0u, ss, o);
    if ((tid & 31) == 0) red[tid >> 5] = ss;
    __syncthreads();
    if (tid == 0){
        float t = red[0] + red[1] + red[2] + red[3];
        s_r = rsqrtf(t/512.f + 1e-5f);
    }
    __syncthreads();
    float r = s_r;
    float4 w4 = *reinterpret_cast<const float4*>(&rms_w[tid*4]);
    v4.x *= r*w4.x; v4.y *= r*w4.y; v4.z *= r*w4.z; v4.w *= r*w4.w;
    *reinterpret_cast<float4*>(&g_yf[(size_t)bl*DI + tid*4]) = v4;
}

// ---------------- K5: out-proj GEMM via tf32 MMA, transposed store ---------
// R15 version: 128x128 tiles. Epilogue emits GroupNorm partials.
__global__ void __launch_bounds__(256) k5_mma(const float* __restrict__ Wout){
    __shared__ uint32_t As[2][16][132];
    __shared__ uint32_t Bs[2][16][132];
    __shared__ float s_part[8][2];
    const int n0 = blockIdx.x * 128;
    const int m0 = blockIdx.y * 128;
    const int tid = threadIdx.x;
    const int wid = tid >> 5, lane = tid & 31;
    const int wm = wid >> 2, wn = wid & 3;
    const int lr = lane >> 2, lc = lane & 3;
    float acc[4][4][4] = {};

    const int t_i  = tid & 127;
    const int t_kq = tid >> 7;

    #pragma unroll
    for (int i = 0; i < 2; i++){
        int kq = t_kq + i*2;
        float4 va = *reinterpret_cast<const float4*>(&g_yf[(size_t)(m0 + t_i)*DI + kq*4]);
        As[0][kq*4+0][t_i]=f2tf32(va.x);
        As[0][kq*4+1][t_i]=f2tf32(va.y);
        As[0][kq*4+2][t_i]=f2tf32(va.z);
        As[0][kq*4+3][t_i]=f2tf32(va.w);
        float4 vb = *reinterpret_cast<const float4*>(&Wout[(size_t)(n0 + t_i)*DI + kq*4]);
        Bs[0][kq*4+0][t_i]=f2tf32(vb.x);
        Bs[0][kq*4+1][t_i]=f2tf32(vb.y);
        Bs[0][kq*4+2][t_i]=f2tf32(vb.z);
        Bs[0][kq*4+3][t_i]=f2tf32(vb.w);
    }
    __syncthreads();

    for (int s = 0; s < 32; s++){
        int buf = s & 1;
        float4 av[2], bv[2];
        if (s < 31){
            int c0 = (s+1)*16;
            #pragma unroll
            for (int i = 0; i < 2; i++){
                int kq = t_kq + i*2;
                av[i] = *reinterpret_cast<const float4*>(&g_yf[(size_t)(m0 + t_i)*DI + c0 + kq*4]);
                bv[i] = *reinterpret_cast<const float4*>(&Wout[(size_t)(n0 + t_i)*DI + c0 + kq*4]);
            }
        }
        #pragma unroll
        for (int ksub = 0; ksub < 2; ksub++){
            int ks = ksub*8;
            uint32_t af[4][4], bf[4][2];
            #pragma unroll
            for (int mi = 0; mi < 4; mi++){
                int mr = wm*64 + mi*16 + lr;
                af[mi][0] = As[buf][ks+lc][mr];
                af[mi][1] = As[buf][ks+lc][mr+8];
                af[mi][2] = As[buf][ks+4+lc][mr];
                af[mi][3] = As[buf][ks+4+lc][mr+8];
            }
            #pragma unroll
            for (int ni = 0; ni < 4; ni++){
                int nc = wn*32 + ni*8 + lr;
                bf[ni][0] = Bs[buf][ks+lc][nc];
                bf[ni][1] = Bs[buf][ks+4+lc][nc];
            }
            #pragma unroll
            for (int mi = 0; mi < 4; mi++)
                #pragma unroll
                for (int ni = 0; ni < 4; ni++)
                    mma_tf32(acc[mi][ni], af[mi], bf[ni]);
        }
        if (s < 31){
            #pragma unroll
            for (int i = 0; i < 2; i++){
                int kq = t_kq + i*2;
                As[buf^1][kq*4+0][t_i]=f2tf32(av[i].x);
                As[buf^1][kq*4+1][t_i]=f2tf32(av[i].y);
                As[buf^1][kq*4+2][t_i]=f2tf32(av[i].z);
                As[buf^1][kq*4+3][t_i]=f2tf32(av[i].w);
                Bs[buf^1][kq*4+0][t_i]=f2tf32(bv[i].x);
                Bs[buf^1][kq*4+1][t_i]=f2tf32(bv[i].y);
                Bs[buf^1][kq*4+2][t_i]=f2tf32(bv[i].z);
                Bs[buf^1][kq*4+3][t_i]=f2tf32(bv[i].w);
            }
            __syncthreads();
        }
    }
    // store transposed + accumulate GroupNorm partials
    float psum = 0.f, psq = 0.f;
    #pragma unroll
    for (int mi = 0; mi < 4; mi++){
        int m = m0 + wm*64 + mi*16 + lr;
        int bb = m >> 10, l = m & 1023;
        #pragma unroll
        for (int ni = 0; ni < 4; ni++){
            int n = n0 + wn*32 + ni*8 + lc*2;
            g_op[((size_t)bb*DM + n  )*Ln + l    ] = acc[mi][ni][0];
            g_op[((size_t)bb*DM + n+1)*Ln + l    ] = acc[mi][ni][1];
            g_op[((size_t)bb*DM + n  )*Ln + l + 8] = acc[mi][ni][2];
            g_op[((size_t)bb*DM + n+1)*Ln + l + 8] = acc[mi][ni][3];
            #pragma unroll
            for (int q = 0; q < 4; q++){
                float vv = acc[mi][ni][q];
                psum += vv; psq += vv*vv;
            }
        }
    }
    #pragma unroll
    for (int o = 16; o; o >>= 1){
        psum += __shfl_xor_sync(~0u, psum, o);
        psq  += __shfl_xor_sync(~0u, psq,  o);
    }
    if (lane == 0){ s_part[wid][0] = psum; s_part[wid][1] = psq; }
    __syncthreads();
    if (tid < 4){
        int g = blockIdx.x*4 + tid;          // global group 0..7
        int b = blockIdx.y >> 3, by = blockIdx.y & 7;
        float S  = s_part[tid][0] + s_part[tid+4][0];
        float S2 = s_part[tid][1] + s_part[tid+4][1];
        int slot = ((b*8 + g)*8 + by)*2;
        g_gnpart[slot]   = S;
        g_gnpart[slot+1] = S2;
    }
}

// ---------------- K7: GN finalize + normalize + affine + Mish (float4) -----
__global__ void __launch_bounds__(256) k7_mish(const float* __restrict__ gn_w,
                        const float* __restrict__ gn_b,
                        float* __restrict__ out){
    __shared__ float s_mu, s_rstd;
    int blk = blockIdx.x;            // b*DM + m
    int b = blk >> 8, m = blk & 255;
    int g = m >> 5;
    if (threadIdx.x == 0){
        double S = 0.0, S2 = 0.0;
        int base = ((b*8 + g)*8)*2;
        #pragma unroll
        for (int by = 0; by < 8; by++){
            S  += (double)g_gnpart[base + by*2];
            S2 += (double)g_gnpart[base + by*2 + 1];
        }
        double N = 32.0*Ln;
        double mu  = S / N;
        double var = S2 / N - mu*mu;
        s_mu   = (float)mu;
        s_rstd = rsqrtf((float)var + 1e-5f);
    }
    __syncthreads();
    float mu = s_mu, r = s_rstd;
    float w = gn_w[m], bo = gn_b[m];
    float4 v4 = *reinterpret_cast<const float4*>(&g_op[(size_t)blk*Ln + threadIdx.x*4]);
    v4.x = fmish((v4.x - mu)*r*w + bo);
    v4.y = fmish((v4.y - mu)*r*w + bo);
    v4.z = fmish((v4.z - mu)*r*w + bo);
    v4.w = fmish((v4.w - mu)*r*w + bo);
    *reinterpret_cast<float4*>(&out[(size_t)blk*Ln + threadIdx.x*4]) = v4;
}

// ---------------------------------------------------------------------------
extern "C" void kernel_launch(void* const* d_in, const int* in_sizes, int n_in,
                              void* d_out, int out_size){
    const float* x       = (const float*)d_in[0];
    const float* W_in    = (const float*)d_in[1];
    const float* conv_w  = (const float*)d_in[2];
    const float* conv_b  = (const float*)d_in[3];
    const float* dt_bias = (const float*)d_in[4];
    const float* A_log   = (const float*)d_in[5];
    const float* Dp      = (const float*)d_in[6];
    const float* rms_w   = (const float*)d_in[7];
    const float* W_out   = (const float*)d_in[8];
    const float* gn_w    = (const float*)d_in[9];
    const float* gn_b    = (const float*)d_in[10];
    float* out = (float*)d_out;

    const int S1_SMEM = (Qc*36*2 + Qc*132 + Qc*68 + Qc*2) * 4;        // ~68.6 KB
    const int S3_SMEM = (Qc*132 + 2*DS*33 + 2*Qc) * 4;                // ~68.1 KB
    cudaFuncSetAttribute(s1_intra, cudaFuncAttributeMaxDynamicSharedMemorySize, S1_SMEM);
    cudaFuncSetAttribute(s3_off,   cudaFuncAttributeMaxDynamicSharedMemorySize, S3_SMEM);

    k1_mma<<<dim3((DIP + 127)/128, (Bn*Ln)/128), 256>>>(x, W_in);
    k2_conv<<<dim3(Ln/4, Bn), 224>>>(conv_w, conv_b, dt_bias);
    s0_gram<<<Bn*NC, 256>>>();
    s1_intra<<<Bn*NC*NH, 256, S1_SMEM>>>(A_log);
    s2_rec<<<Bn*NH, 512>>>();
    s3_off<<<Bn*NC*(NH/2), 256, S3_SMEM>>>(Dp);
    k4_gate<<<Bn*Ln, 128>>>(rms_w);
    k5_mma<<<dim3(DM/128, (Bn*Ln)/128), 256>>>(W_out);
    k7_mish<<<Bn*DM, 256>>>(gn_w, gn_b, out);
}